// round 15
// baseline (speedup 1.0000x reference)
#include <cuda_runtime.h>
#include <cuda_bf16.h>
#include <cstdint>
#include <math.h>

#define Tn  4096
#define INn 512
#define Kn  64
#define Vn  64
#define Hn  4096
#define CH  64
#define NCH (Tn / CH)

// ---------------- scratch (device globals; no cudaMalloc allowed) -----------
__device__ float g_k  [Tn * Kn];
__device__ float g_q  [Tn * Kn];
__device__ float g_v  [Tn * Vn];
__device__ float g_h3 [Tn * Hn];
__device__ float g_wqkv[192 * INn];
__device__ __nv_bfloat16 g_attb[Tn * Vn];
__device__ __nv_bfloat16 g_h1b [Tn * Hn];
__device__ __nv_bfloat16 g_h2b [Tn * Hn];
__device__ __nv_bfloat16 g_w1b [Hn * Vn];
__device__ __nv_bfloat16 g_w2b [(size_t)Hn * Hn];
__device__ __nv_bfloat16 g_w3b [(size_t)Hn * Hn];
__device__ __nv_bfloat16 g_xcat3[(size_t)Tn * 3 * INn];   // [xh | xh | xl]
__device__ __nv_bfloat16 g_wcat3[(size_t)Hn * 3 * INn];   // [Wsh | Wsl | Wsh]
__device__ float g_L  [NCH * Kn * Vn];
__device__ float g_Sin[NCH * Kn * Vn];
__device__ float g_Lz [NCH * Kn];
__device__ float g_Zin[NCH * Kn];
__device__ int   g_keep[NCH];

// ---------------- activations ----------------------------------------------
__device__ __forceinline__ float mishf(float x) {
    if (x > 20.f) return x;
    float u = expf(x);
    float w = u * (u + 2.f);
    return x * w / (w + 2.f);
}

// ---------------- async copy helpers ------------------------------------------
__device__ __forceinline__ void cp_async16(uint32_t saddr, const void* gaddr) {
    asm volatile("cp.async.cg.shared.global [%0], [%1], 16;\n" :: "r"(saddr), "l"(gaddr));
}
__device__ __forceinline__ void cp_commit() { asm volatile("cp.async.commit_group;\n"); }
template <int N>
__device__ __forceinline__ void cp_wait() { asm volatile("cp.async.wait_group %0;\n" :: "n"(N)); }

__device__ __forceinline__ void mma_bf16(float* d, const uint32_t* a, const uint32_t* b) {
    asm volatile(
        "mma.sync.aligned.m16n8k16.row.col.f32.bf16.bf16.f32 "
        "{%0,%1,%2,%3}, {%4,%5,%6,%7}, {%8,%9}, {%0,%1,%2,%3};\n"
        : "+f"(d[0]), "+f"(d[1]), "+f"(d[2]), "+f"(d[3])
        : "r"(a[0]), "r"(a[1]), "r"(a[2]), "r"(a[3]), "r"(b[0]), "r"(b[1]));
}

// ======================= bf16 tensor-core GEMM ================================
// C[M,N] = A[M,K] * W[N,K]^T (+bias). m16n8k16 bf16 mma, fp32 accumulate.
// 256x128 CTA tile (64x64 warp tiles -> mma:ldsm = 4:1 vs 2.7:1 at 64x32),
// K-chunks of 32, 4-stage cp.async pipeline. Dynamic smem: stage s at s*30720;
// A rows (stride 80B) at +0 (256 rows), W at +20480 (128 rows).
#define BKB 32
#define NSTAGE 4
#define STG 30720
#define GEMM_SMEM (NSTAGE * STG)   // 122880 bytes

// EPI: 0 = fp32 store (acc+bias) ; 1 = mish(acc+bias) -> bf16 store
//      2 = fp32 accumulate (C += acc + bias)
template <int EPI>
__global__ __launch_bounds__(256, 1)
void gemm_bf16(const __nv_bfloat16* __restrict__ A, const __nv_bfloat16* __restrict__ W,
               const float* __restrict__ bias, void* __restrict__ Cv,
               int M, int N, int K)
{
    extern __shared__ __align__(16) char smem_raw[];
    const uint32_t sb = (uint32_t)__cvta_generic_to_shared(smem_raw);

    const int tid  = threadIdx.x;
    const int lane = tid & 31;
    const int wid  = tid >> 5;
    const int g    = lane >> 2;
    const int tig  = lane & 3;
    const int wm   = (wid & 3) * 64;     // 4 warps across M=256
    const int wn   = (wid >> 2) * 64;    // 2 warps across N=128
    const int m0   = blockIdx.y * 256;
    const int n0   = blockIdx.x * 128;

    // loads: every thread loads A row tid; threads <128 also load B row tid
    const __nv_bfloat16* gA = A + (size_t)(m0 + tid) * K;
    const __nv_bfloat16* gB = (tid < 128) ? (W + (size_t)(n0 + tid) * K) : nullptr;
    const uint32_t srowA = (uint32_t)tid * 80u;
    const uint32_t srowB = 20480u + (uint32_t)tid * 80u;

    float acc[4][8][4];
#pragma unroll
    for (int mt = 0; mt < 4; mt++)
#pragma unroll
        for (int nt = 0; nt < 8; nt++)
#pragma unroll
            for (int r = 0; r < 4; r++) acc[mt][nt][r] = 0.f;

    const int niter = K / BKB;

    auto issue = [&](int stg, int src) {
        uint32_t base = sb + (uint32_t)stg * STG;
        const __nv_bfloat16* gp = gA + (size_t)src * BKB;
#pragma unroll
        for (int ch = 0; ch < 4; ch++)
            cp_async16(base + srowA + ch * 16, gp + ch * 8);
        if (gB) {
            const __nv_bfloat16* gq = gB + (size_t)src * BKB;
#pragma unroll
            for (int ch = 0; ch < 4; ch++)
                cp_async16(base + srowB + ch * 16, gq + ch * 8);
        }
        cp_commit();
    };

    issue(0, 0);
    issue(1, niter > 1 ? 1 : niter - 1);
    issue(2, niter > 2 ? 2 : niter - 1);

    const int a_m  = lane & 15;
    const int a_k  = (lane >> 4) * 8;
    const int b_g8 = lane >> 3;
    const int b_n  = (lane & 7) + 8 * (b_g8 >> 1);
    const int b_k  = (b_g8 & 1) * 8;

    for (int it = 0; it < niter; it++) {
        cp_wait<2>();
        __syncthreads();

        {
            int nx = it + 3; if (nx >= niter) nx = niter - 1;
            issue((it + 3) & 3, nx);
        }

        const uint32_t stga = sb + (uint32_t)(it & 3) * STG;
        const uint32_t stgb = stga + 20480u;
#pragma unroll
        for (int kk = 0; kk < BKB; kk += 16) {
            uint32_t a[4][4], b[8][2];
#pragma unroll
            for (int mt = 0; mt < 4; mt++) {
                uint32_t sa = stga + (uint32_t)(wm + 16 * mt + a_m) * 80u
                                   + (uint32_t)(kk + a_k) * 2u;
                asm volatile("ldmatrix.sync.aligned.m8n8.x4.shared.b16 {%0,%1,%2,%3}, [%4];"
                    : "=r"(a[mt][0]), "=r"(a[mt][1]), "=r"(a[mt][2]), "=r"(a[mt][3])
                    : "r"(sa));
            }
#pragma unroll
            for (int p = 0; p < 4; p++) {
                uint32_t sbb = stgb + (uint32_t)(wn + 16 * p + b_n) * 80u
                                    + (uint32_t)(kk + b_k) * 2u;
                asm volatile("ldmatrix.sync.aligned.m8n8.x4.shared.b16 {%0,%1,%2,%3}, [%4];"
                    : "=r"(b[2 * p][0]), "=r"(b[2 * p][1]),
                      "=r"(b[2 * p + 1][0]), "=r"(b[2 * p + 1][1])
                    : "r"(sbb));
            }
#pragma unroll
            for (int mt = 0; mt < 4; mt++)
#pragma unroll
                for (int nt = 0; nt < 8; nt++)
                    mma_bf16(acc[mt][nt], a[mt], b[nt]);
        }
    }

#pragma unroll
    for (int mt = 0; mt < 4; mt++) {
#pragma unroll
        for (int nt = 0; nt < 8; nt++) {
            int r0 = m0 + wm + 16 * mt + g;
            int cc = n0 + wn + 8 * nt + 2 * tig;
            float bs0 = bias ? bias[cc]     : 0.f;
            float bs1 = bias ? bias[cc + 1] : 0.f;
            float v0 = acc[mt][nt][0] + bs0;
            float v1 = acc[mt][nt][1] + bs1;
            float v2 = acc[mt][nt][2] + bs0;
            float v3 = acc[mt][nt][3] + bs1;
            if (EPI == 1) {
                __nv_bfloat16* C = (__nv_bfloat16*)Cv;
                C[(size_t)r0 * N + cc]           = __float2bfloat16(mishf(v0));
                C[(size_t)r0 * N + cc + 1]       = __float2bfloat16(mishf(v1));
                C[(size_t)(r0 + 8) * N + cc]     = __float2bfloat16(mishf(v2));
                C[(size_t)(r0 + 8) * N + cc + 1] = __float2bfloat16(mishf(v3));
            } else if (EPI == 0) {
                float* C = (float*)Cv;
                C[(size_t)r0 * N + cc]           = v0;
                C[(size_t)r0 * N + cc + 1]       = v1;
                C[(size_t)(r0 + 8) * N + cc]     = v2;
                C[(size_t)(r0 + 8) * N + cc + 1] = v3;
            } else {
                float* C = (float*)Cv;
                C[(size_t)r0 * N + cc]           += v0;
                C[(size_t)r0 * N + cc + 1]       += v1;
                C[(size_t)(r0 + 8) * N + cc]     += v2;
                C[(size_t)(r0 + 8) * N + cc + 1] += v3;
            }
        }
    }
}

// ---------------- conversions --------------------------------------------------
// vectorized fp32 -> bf16 (4 elems/thread)
__global__ void f2bf4(const float4* __restrict__ in, uint2* __restrict__ out, int n4) {
    int i = blockIdx.x * 256 + threadIdx.x;
    if (i < n4) {
        float4 v = in[i];
        __nv_bfloat162 lo = __floats2bfloat162_rn(v.x, v.y);
        __nv_bfloat162 hi = __floats2bfloat162_rn(v.z, v.w);
        uint2 o;
        o.x = *(const uint32_t*)&lo;
        o.y = *(const uint32_t*)&hi;
        out[i] = o;
    }
}
// split for x: [xh | xh | xl] rows of 1536
__global__ void split_x3(const float* __restrict__ in, __nv_bfloat16* __restrict__ cat, int n) {
    int i = blockIdx.x * 256 + threadIdx.x;
    if (i < n) {
        float v = in[i];
        __nv_bfloat16 h = __float2bfloat16(v);
        __nv_bfloat16 l = __float2bfloat16(v - __bfloat162float(h));
        int r = i / INn, c = i % INn;
        size_t base = (size_t)r * (3 * INn) + c;
        cat[base]            = h;
        cat[base + INn]      = h;
        cat[base + 2 * INn]  = l;
    }
}
// split for W: [Wsh | Wsl | Wsh]
__global__ void split_w3(const float* __restrict__ in, __nv_bfloat16* __restrict__ cat, int n) {
    int i = blockIdx.x * 256 + threadIdx.x;
    if (i < n) {
        float v = in[i];
        __nv_bfloat16 h = __float2bfloat16(v);
        __nv_bfloat16 l = __float2bfloat16(v - __bfloat162float(h));
        int r = i / INn, c = i % INn;
        size_t base = (size_t)r * (3 * INn) + c;
        cat[base]            = h;
        cat[base + INn]      = l;
        cat[base + 2 * INn]  = h;
    }
}

// ---------------- fused qkv GEMM (exact fp32) ---------------------------------
__global__ __launch_bounds__(256)
void qkv_gemm(const float* __restrict__ x, const float* __restrict__ Wc,
              const float* __restrict__ bv,
              float* __restrict__ ko, float* __restrict__ qo, float* __restrict__ vo)
{
    __shared__ float As[16][64];
    __shared__ float Bs[16][64];
    const int tid = threadIdx.x;
    const int tx = tid & 15, ty = tid >> 4;
    const int m0 = blockIdx.y * 64, n0 = blockIdx.x * 64;
    const int lrow = tid >> 2, lk = (tid & 3) * 4;

    float acc[4][4];
#pragma unroll
    for (int i = 0; i < 4; i++)
#pragma unroll
        for (int j = 0; j < 4; j++) acc[i][j] = 0.f;

    for (int k0 = 0; k0 < INn; k0 += 16) {
        float4 av = *(const float4*)(x  + (size_t)(m0 + lrow) * INn + k0 + lk);
        float4 bw = *(const float4*)(Wc + (size_t)(n0 + lrow) * INn + k0 + lk);
        As[lk + 0][lrow] = av.x; As[lk + 1][lrow] = av.y;
        As[lk + 2][lrow] = av.z; As[lk + 3][lrow] = av.w;
        Bs[lk + 0][lrow] = bw.x; Bs[lk + 1][lrow] = bw.y;
        Bs[lk + 2][lrow] = bw.z; Bs[lk + 3][lrow] = bw.w;
        __syncthreads();
#pragma unroll
        for (int kk = 0; kk < 16; kk++) {
            float a[4], b[4];
#pragma unroll
            for (int u = 0; u < 4; u++) { a[u] = As[kk][ty * 4 + u]; b[u] = Bs[kk][tx * 4 + u]; }
#pragma unroll
            for (int i = 0; i < 4; i++)
#pragma unroll
                for (int j = 0; j < 4; j++)
                    acc[i][j] = fmaf(a[i], b[j], acc[i][j]);
        }
        __syncthreads();
    }

#pragma unroll
    for (int i = 0; i < 4; i++) {
        int m = m0 + ty * 4 + i;
#pragma unroll
        for (int j = 0; j < 4; j++) {
            int n = n0 + tx * 4 + j;
            float vv = acc[i][j];
            if (n < 64)       ko[m * 64 + n]       = (vv > 0.f) ? (1.f + vv) : expf(vv);
            else if (n < 128) qo[m * 64 + n - 64]  = (vv > 0.f) ? (1.f + vv) : expf(vv);
            else              vo[m * 64 + n - 128] = vv + bv[n - 128];
        }
    }
}

// ---------------- chunked segmented scan --------------------------------------
__global__ __launch_bounds__(64)
void scan_carry(const float* __restrict__ k, const float* __restrict__ v,
                const int* __restrict__ start,
                float* __restrict__ L, float* __restrict__ Lz, int* __restrict__ keepf)
{
    __shared__ float kbuf[CH];
    __shared__ int   sbuf[CH];
    const int c = blockIdx.x, i = blockIdx.y, j = threadIdx.x;
    const int t0 = c * CH;
    kbuf[j] = k[(size_t)(t0 + j) * Kn + i];
    sbuf[j] = start[t0 + j];
    __syncthreads();

    float run = 0.f, zr = 0.f;
    int anyst = 0;
    for (int tt = 0; tt < CH; tt++) {
        if (sbuf[tt]) { run = 0.f; zr = 0.f; anyst = 1; }
        float kt = kbuf[tt];
        run = fmaf(kt, v[(size_t)(t0 + tt) * Vn + j], run);
        zr += kt;
    }
    L[c * (Kn * Vn) + i * Vn + j] = run;
    if (j == 0) Lz[c * Kn + i] = zr;
    if (i == 0 && j == 0) keepf[c] = !anyst;
}

__global__ __launch_bounds__(1024)
void scan_combine(const float* __restrict__ s0, const float* __restrict__ z0,
                  const float* __restrict__ L, const float* __restrict__ Lz,
                  const int* __restrict__ keepf,
                  float* __restrict__ Sin, float* __restrict__ Zin)
{
    const int tid = threadIdx.x;
    float S[4];
#pragma unroll
    for (int u = 0; u < 4; u++) S[u] = s0[tid * 4 + u];
    float Z = (tid < Kn) ? z0[tid] : 0.f;

    for (int c = 0; c < NCH; c++) {
#pragma unroll
        for (int u = 0; u < 4; u++) Sin[c * (Kn * Vn) + tid * 4 + u] = S[u];
        if (tid < Kn) Zin[c * Kn + tid] = Z;
        int kp = keepf[c];
#pragma unroll
        for (int u = 0; u < 4; u++)
            S[u] = (kp ? S[u] : 0.f) + L[c * (Kn * Vn) + tid * 4 + u];
        if (tid < Kn) Z = (kp ? Z : 0.f) + Lz[c * Kn + tid];
    }
}

__global__ __launch_bounds__(64)
void scan_out(const float* __restrict__ k, const float* __restrict__ v,
              const int* __restrict__ start,
              const float* __restrict__ Sin, const float* __restrict__ Zin,
              float* __restrict__ out_s, float* __restrict__ out_z)
{
    __shared__ float kbuf[CH];
    __shared__ int   sbuf[CH];
    const int c = blockIdx.x, i = blockIdx.y, j = threadIdx.x;
    const int t0 = c * CH;
    kbuf[j] = k[(size_t)(t0 + j) * Kn + i];
    sbuf[j] = start[t0 + j];
    __syncthreads();

    float run = Sin[c * (Kn * Vn) + i * Vn + j];
    float zr  = Zin[c * Kn + i];
    for (int tt = 0; tt < CH; tt++) {
        if (sbuf[tt]) { run = 0.f; zr = 0.f; }
        float kt = kbuf[tt];
        run = fmaf(kt, v[(size_t)(t0 + tt) * Vn + j], run);
        zr += kt;
        out_s[(size_t)(t0 + tt) * (Kn * Vn) + i * Vn + j] = run;
        if (j == 0) out_z[(size_t)(t0 + tt) * Kn + i] = zr;
    }
}

// ---------------- attention output (writes bf16 att) -------------------------
__global__ __launch_bounds__(64)
void attn_kernel(const float* __restrict__ s, const float* __restrict__ z,
                 const float* __restrict__ q, __nv_bfloat16* __restrict__ outp)
{
    __shared__ float qs[64];
    __shared__ float zs[64];
    __shared__ float dsh;

    const int t = blockIdx.x, j = threadIdx.x;
    qs[j] = q[t * 64 + j];
    zs[j] = z[t * 64 + j];
    __syncthreads();
    if (j == 0) {
        float qsum = 0.f, zsum = 0.f;
        for (int i = 0; i < 64; i++) { qsum += qs[i]; zsum += zs[i]; }
        dsh = fmaxf(zsum * qsum, 1e-6f);
    }
    __syncthreads();

    float acc = 0.f;
    const float* sp = s + (size_t)t * 4096;
#pragma unroll 8
    for (int i = 0; i < 64; i++)
        acc = fmaf(sp[i * 64 + j], qs[i], acc);
    outp[t * 64 + j] = __float2bfloat16(acc / dsh);
}

// ---------------- LayerNorm over H ------------------------------------------
__global__ __launch_bounds__(256)
void ln_kernel(const float* __restrict__ h, const float* __restrict__ g,
               const float* __restrict__ b, float* __restrict__ o)
{
    __shared__ float red[256];
    const int t = blockIdx.x, tid = threadIdx.x;
    const float* hp = h + (size_t)t * Hn;

    float loc[16];
    float sum = 0.f;
#pragma unroll
    for (int u = 0; u < 16; u++) { loc[u] = hp[tid + u * 256]; sum += loc[u]; }
    red[tid] = sum; __syncthreads();
    for (int s = 128; s > 0; s >>= 1) { if (tid < s) red[tid] += red[tid + s]; __syncthreads(); }
    float mu = red[0] * (1.f / Hn);
    __syncthreads();

    float sq = 0.f;
#pragma unroll
    for (int u = 0; u < 16; u++) { float d = loc[u] - mu; sq += d * d; }
    red[tid] = sq; __syncthreads();
    for (int s = 128; s > 0; s >>= 1) { if (tid < s) red[tid] += red[tid + s]; __syncthreads(); }
    float inv = rsqrtf(red[0] * (1.f / Hn) + 1e-5f);

#pragma unroll
    for (int u = 0; u < 16; u++) {
        int idx = tid + u * 256;
        o[(size_t)t * Hn + idx] = (loc[u] - mu) * inv * g[idx] + b[idx];
    }
}

// ---------------- launch ----------------------------------------------------
extern "C" void kernel_launch(void* const* d_in, const int* in_sizes, int n_in,
                              void* d_out, int out_size)
{
    const float* x     = (const float*)d_in[0];
    const float* s0    = (const float*)d_in[1];
    const float* z0    = (const float*)d_in[2];
    const int*   start = (const int*)d_in[3];
    const float* Wk    = (const float*)d_in[5];
    const float* Wq    = (const float*)d_in[6];
    const float* Wv    = (const float*)d_in[7];
    const float* bv    = (const float*)d_in[8];
    const float* Wskip = (const float*)d_in[9];
    const float* bskip = (const float*)d_in[10];
    const float* W1    = (const float*)d_in[11];
    const float* b1    = (const float*)d_in[12];
    const float* W2    = (const float*)d_in[13];
    const float* b2    = (const float*)d_in[14];
    const float* W3    = (const float*)d_in[15];
    const float* b3    = (const float*)d_in[16];
    const float* ln_g  = (const float*)d_in[17];
    const float* ln_b  = (const float*)d_in[18];

    float* out    = (float*)d_out;
    float* out_hn = out;
    float* out_s  = out + (size_t)Tn * Hn;
    float* out_z  = out_s + (size_t)Tn * Kn * Vn;

    float *gk, *gq, *gv, *gh3, *gwqkv, *gL, *gSin, *gLz, *gZin;
    int* gkeep;
    __nv_bfloat16 *gattb, *gh1b, *gh2b, *gw1b, *gw2b, *gw3b, *gxcat3, *gwcat3;
    cudaGetSymbolAddress((void**)&gk,     g_k);
    cudaGetSymbolAddress((void**)&gq,     g_q);
    cudaGetSymbolAddress((void**)&gv,     g_v);
    cudaGetSymbolAddress((void**)&gh3,    g_h3);
    cudaGetSymbolAddress((void**)&gwqkv,  g_wqkv);
    cudaGetSymbolAddress((void**)&gattb,  g_attb);
    cudaGetSymbolAddress((void**)&gh1b,   g_h1b);
    cudaGetSymbolAddress((void**)&gh2b,   g_h2b);
    cudaGetSymbolAddress((void**)&gw1b,   g_w1b);
    cudaGetSymbolAddress((void**)&gw2b,   g_w2b);
    cudaGetSymbolAddress((void**)&gw3b,   g_w3b);
    cudaGetSymbolAddress((void**)&gxcat3, g_xcat3);
    cudaGetSymbolAddress((void**)&gwcat3, g_wcat3);
    cudaGetSymbolAddress((void**)&gL,     g_L);
    cudaGetSymbolAddress((void**)&gSin,   g_Sin);
    cudaGetSymbolAddress((void**)&gLz,    g_Lz);
    cudaGetSymbolAddress((void**)&gZin,   g_Zin);
    cudaGetSymbolAddress((void**)&gkeep,  g_keep);

    cudaFuncSetAttribute(gemm_bf16<0>, cudaFuncAttributeMaxDynamicSharedMemorySize, GEMM_SMEM);
    cudaFuncSetAttribute(gemm_bf16<1>, cudaFuncAttributeMaxDynamicSharedMemorySize, GEMM_SMEM);
    cudaFuncSetAttribute(gemm_bf16<2>, cudaFuncAttributeMaxDynamicSharedMemorySize, GEMM_SMEM);

    dim3 blk(256);
    auto grd = [](int M, int N) { return dim3(N / 128, M / 256); };
    auto cgrd = [](int n) { return dim3((n + 255) / 256); };

    cudaMemcpyAsync(gwqkv,             Wk, 64 * INn * 4, cudaMemcpyDeviceToDevice);
    cudaMemcpyAsync(gwqkv +  64 * INn, Wq, 64 * INn * 4, cudaMemcpyDeviceToDevice);
    cudaMemcpyAsync(gwqkv + 128 * INn, Wv, 64 * INn * 4, cudaMemcpyDeviceToDevice);

    f2bf4<<<cgrd(Hn * Vn / 4), blk>>>((const float4*)W1, (uint2*)gw1b, Hn * Vn / 4);
    f2bf4<<<cgrd(Hn * Hn / 4), blk>>>((const float4*)W2, (uint2*)gw2b, Hn * Hn / 4);
    f2bf4<<<cgrd(Hn * Hn / 4), blk>>>((const float4*)W3, (uint2*)gw3b, Hn * Hn / 4);
    split_x3<<<cgrd(Tn * INn), blk>>>(x, gxcat3, Tn * INn);
    split_w3<<<cgrd(Hn * INn), blk>>>(Wskip, gwcat3, Hn * INn);

    qkv_gemm<<<dim3(3, 64), blk>>>(x, gwqkv, bv, gk, gq, gv);

    scan_carry<<<dim3(NCH, Kn), 64>>>(gk, gv, start, gL, gLz, gkeep);
    scan_combine<<<1, 1024>>>(s0, z0, gL, gLz, gkeep, gSin, gZin);
    scan_out<<<dim3(NCH, Kn), 64>>>(gk, gv, start, gSin, gZin, out_s, out_z);

    attn_kernel<<<Tn, 64>>>(out_s, out_z, gq, gattb);

    // MLP on bf16 tensor cores (256x128 tile, 4-stage)
    gemm_bf16<1><<<grd(Tn, Hn), blk, GEMM_SMEM>>>(gattb, gw1b, b1, gh1b, Tn, Hn, Vn);
    gemm_bf16<1><<<grd(Tn, Hn), blk, GEMM_SMEM>>>(gh1b, gw2b, b2, gh2b, Tn, Hn, Hn);
    gemm_bf16<0><<<grd(Tn, Hn), blk, GEMM_SMEM>>>(gh2b, gw3b, b3, gh3, Tn, Hn, Hn);

    // skip: ONE fused split-bf16 GEMM, K=1536 ([xh|xh|xl] . [Wsh|Wsl|Wsh]^T)
    gemm_bf16<2><<<grd(Tn, Hn), blk, GEMM_SMEM>>>(gxcat3, gwcat3, bskip, gh3, Tn, Hn, 3 * INn);

    ln_kernel<<<Tn, 256>>>(gh3, ln_g, ln_b, out_hn);
}

// round 16
// speedup vs baseline: 1.0958x; 1.0958x over previous
#include <cuda_runtime.h>
#include <cuda_bf16.h>
#include <cstdint>
#include <math.h>

#define Tn  4096
#define INn 512
#define Kn  64
#define Vn  64
#define Hn  4096
#define CH  64
#define NCH (Tn / CH)

// ---------------- scratch (device globals; no cudaMalloc allowed) -----------
__device__ float g_k  [Tn * Kn];
__device__ float g_q  [Tn * Kn];
__device__ float g_v  [Tn * Vn];
__device__ float g_h3 [Tn * Hn];
__device__ float g_wqkv[192 * INn];
__device__ __nv_bfloat16 g_attb[Tn * Vn];
__device__ __nv_bfloat16 g_h1b [Tn * Hn];
__device__ __nv_bfloat16 g_h2b [Tn * Hn];
__device__ __nv_bfloat16 g_w1b [Hn * Vn];
__device__ __nv_bfloat16 g_w2b [(size_t)Hn * Hn];
__device__ __nv_bfloat16 g_w3b [(size_t)Hn * Hn];
__device__ __nv_bfloat16 g_xcat3[(size_t)Tn * 3 * INn];   // [xh | xh | xl]
__device__ __nv_bfloat16 g_wcat3[(size_t)Hn * 3 * INn];   // [Wsh | Wsl | Wsh]
__device__ float g_L  [NCH * Kn * Vn];
__device__ float g_Sin[NCH * Kn * Vn];
__device__ float g_Lz [NCH * Kn];
__device__ float g_Zin[NCH * Kn];
__device__ int   g_keep[NCH];

// ---------------- activations ----------------------------------------------
__device__ __forceinline__ float mishf(float x) {
    if (x > 20.f) return x;
    float u = expf(x);
    float w = u * (u + 2.f);
    return x * w / (w + 2.f);
}

// ---------------- async copy helpers ------------------------------------------
__device__ __forceinline__ void cp_async16(uint32_t saddr, const void* gaddr) {
    asm volatile("cp.async.cg.shared.global [%0], [%1], 16;\n" :: "r"(saddr), "l"(gaddr));
}
__device__ __forceinline__ void cp_commit() { asm volatile("cp.async.commit_group;\n"); }
template <int N>
__device__ __forceinline__ void cp_wait() { asm volatile("cp.async.wait_group %0;\n" :: "n"(N)); }

__device__ __forceinline__ void mma_bf16(float* d, const uint32_t* a, const uint32_t* b) {
    asm volatile(
        "mma.sync.aligned.m16n8k16.row.col.f32.bf16.bf16.f32 "
        "{%0,%1,%2,%3}, {%4,%5,%6,%7}, {%8,%9}, {%0,%1,%2,%3};\n"
        : "+f"(d[0]), "+f"(d[1]), "+f"(d[2]), "+f"(d[3])
        : "r"(a[0]), "r"(a[1]), "r"(a[2]), "r"(a[3]), "r"(b[0]), "r"(b[1]));
}

// ======================= bf16 tensor-core GEMM ================================
// r14 configuration (best known): 128x128 CTA tile, 64x32 warp tiles, K-chunks
// of 32, 4-stage cp.async pipeline, 2 CTAs/SM. m16n8k16 bf16 mma, fp32 accum.
// Dynamic smem: stage s at s*20480; A rows (stride 80B) at +0, W at +10240.
#define BKB 32
#define NSTAGE 4
#define STG 20480
#define GEMM_SMEM (NSTAGE * STG)   // 81920 bytes

// EPI: 0 = fp32 store (acc+bias) ; 1 = mish(acc+bias) -> bf16 store
//      2 = fp32 accumulate (C += acc + bias)
template <int EPI>
__global__ __launch_bounds__(256)
void gemm_bf16(const __nv_bfloat16* __restrict__ A, const __nv_bfloat16* __restrict__ W,
               const float* __restrict__ bias, void* __restrict__ Cv,
               int M, int N, int K)
{
    extern __shared__ __align__(16) char smem_raw[];
    const uint32_t sb = (uint32_t)__cvta_generic_to_shared(smem_raw);

    const int tid  = threadIdx.x;
    const int lane = tid & 31;
    const int wid  = tid >> 5;
    const int g    = lane >> 2;
    const int tig  = lane & 3;
    const int wm   = (wid & 1) * 64;
    const int wn   = (wid >> 1) * 32;
    const int m0   = blockIdx.y * 128;
    const int n0   = blockIdx.x * 128;

    const int ld_row = tid & 127;
    const bool is_a  = tid < 128;
    const __nv_bfloat16* gbase = is_a ? (A + (size_t)(m0 + ld_row) * K)
                                      : (W + (size_t)(n0 + ld_row) * K);
    const uint32_t srow = (is_a ? 0u : 10240u) + (uint32_t)ld_row * 80u;

    float acc[4][4][4];
#pragma unroll
    for (int mt = 0; mt < 4; mt++)
#pragma unroll
        for (int nt = 0; nt < 4; nt++)
#pragma unroll
            for (int r = 0; r < 4; r++) acc[mt][nt][r] = 0.f;

    const int niter = K / BKB;

    auto issue = [&](int stg, int src) {
        uint32_t sa = sb + (uint32_t)stg * STG + srow;
        const __nv_bfloat16* gp = gbase + (size_t)src * BKB;
#pragma unroll
        for (int ch = 0; ch < 4; ch++)
            cp_async16(sa + ch * 16, gp + ch * 8);
        cp_commit();
    };

    issue(0, 0);
    issue(1, niter > 1 ? 1 : niter - 1);
    issue(2, niter > 2 ? 2 : niter - 1);

    const int a_m  = lane & 15;
    const int a_k  = (lane >> 4) * 8;
    const int b_g8 = lane >> 3;
    const int b_n  = (lane & 7) + 8 * (b_g8 >> 1);
    const int b_k  = (b_g8 & 1) * 8;

    for (int it = 0; it < niter; it++) {
        cp_wait<2>();
        __syncthreads();

        {
            int nx = it + 3; if (nx >= niter) nx = niter - 1;
            issue((it + 3) & 3, nx);
        }

        const uint32_t stga = sb + (uint32_t)(it & 3) * STG;
        const uint32_t stgb = stga + 10240u;
#pragma unroll
        for (int kk = 0; kk < BKB; kk += 16) {
            uint32_t a[4][4], b[4][2];
#pragma unroll
            for (int mt = 0; mt < 4; mt++) {
                uint32_t sa = stga + (uint32_t)(wm + 16 * mt + a_m) * 80u
                                   + (uint32_t)(kk + a_k) * 2u;
                asm volatile("ldmatrix.sync.aligned.m8n8.x4.shared.b16 {%0,%1,%2,%3}, [%4];"
                    : "=r"(a[mt][0]), "=r"(a[mt][1]), "=r"(a[mt][2]), "=r"(a[mt][3])
                    : "r"(sa));
            }
#pragma unroll
            for (int p = 0; p < 2; p++) {
                uint32_t sbb = stgb + (uint32_t)(wn + 16 * p + b_n) * 80u
                                    + (uint32_t)(kk + b_k) * 2u;
                asm volatile("ldmatrix.sync.aligned.m8n8.x4.shared.b16 {%0,%1,%2,%3}, [%4];"
                    : "=r"(b[2 * p][0]), "=r"(b[2 * p][1]),
                      "=r"(b[2 * p + 1][0]), "=r"(b[2 * p + 1][1])
                    : "r"(sbb));
            }
#pragma unroll
            for (int mt = 0; mt < 4; mt++)
#pragma unroll
                for (int nt = 0; nt < 4; nt++)
                    mma_bf16(acc[mt][nt], a[mt], b[nt]);
        }
    }

#pragma unroll
    for (int mt = 0; mt < 4; mt++) {
#pragma unroll
        for (int nt = 0; nt < 4; nt++) {
            int r0 = m0 + wm + 16 * mt + g;
            int cc = n0 + wn + 8 * nt + 2 * tig;
            float bs0 = bias ? bias[cc]     : 0.f;
            float bs1 = bias ? bias[cc + 1] : 0.f;
            float v0 = acc[mt][nt][0] + bs0;
            float v1 = acc[mt][nt][1] + bs1;
            float v2 = acc[mt][nt][2] + bs0;
            float v3 = acc[mt][nt][3] + bs1;
            if (EPI == 1) {
                __nv_bfloat16* C = (__nv_bfloat16*)Cv;
                C[(size_t)r0 * N + cc]           = __float2bfloat16(mishf(v0));
                C[(size_t)r0 * N + cc + 1]       = __float2bfloat16(mishf(v1));
                C[(size_t)(r0 + 8) * N + cc]     = __float2bfloat16(mishf(v2));
                C[(size_t)(r0 + 8) * N + cc + 1] = __float2bfloat16(mishf(v3));
            } else if (EPI == 0) {
                float* C = (float*)Cv;
                C[(size_t)r0 * N + cc]           = v0;
                C[(size_t)r0 * N + cc + 1]       = v1;
                C[(size_t)(r0 + 8) * N + cc]     = v2;
                C[(size_t)(r0 + 8) * N + cc + 1] = v3;
            } else {
                float* C = (float*)Cv;
                C[(size_t)r0 * N + cc]           += v0;
                C[(size_t)r0 * N + cc + 1]       += v1;
                C[(size_t)(r0 + 8) * N + cc]     += v2;
                C[(size_t)(r0 + 8) * N + cc + 1] += v3;
            }
        }
    }
}

// ---------------- conversions --------------------------------------------------
// vectorized fp32 -> bf16 (4 elems/thread)
__global__ void f2bf4(const float4* __restrict__ in, uint2* __restrict__ out, int n4) {
    int i = blockIdx.x * 256 + threadIdx.x;
    if (i < n4) {
        float4 v = in[i];
        __nv_bfloat162 lo = __floats2bfloat162_rn(v.x, v.y);
        __nv_bfloat162 hi = __floats2bfloat162_rn(v.z, v.w);
        uint2 o;
        o.x = *(const uint32_t*)&lo;
        o.y = *(const uint32_t*)&hi;
        out[i] = o;
    }
}
// split for x: [xh | xh | xl] rows of 1536
__global__ void split_x3(const float* __restrict__ in, __nv_bfloat16* __restrict__ cat, int n) {
    int i = blockIdx.x * 256 + threadIdx.x;
    if (i < n) {
        float v = in[i];
        __nv_bfloat16 h = __float2bfloat16(v);
        __nv_bfloat16 l = __float2bfloat16(v - __bfloat162float(h));
        int r = i / INn, c = i % INn;
        size_t base = (size_t)r * (3 * INn) + c;
        cat[base]            = h;
        cat[base + INn]      = h;
        cat[base + 2 * INn]  = l;
    }
}
// split for W: [Wsh | Wsl | Wsh]
__global__ void split_w3(const float* __restrict__ in, __nv_bfloat16* __restrict__ cat, int n) {
    int i = blockIdx.x * 256 + threadIdx.x;
    if (i < n) {
        float v = in[i];
        __nv_bfloat16 h = __float2bfloat16(v);
        __nv_bfloat16 l = __float2bfloat16(v - __bfloat162float(h));
        int r = i / INn, c = i % INn;
        size_t base = (size_t)r * (3 * INn) + c;
        cat[base]            = h;
        cat[base + INn]      = l;
        cat[base + 2 * INn]  = h;
    }
}

// ---------------- fused qkv GEMM (exact fp32) ---------------------------------
__global__ __launch_bounds__(256)
void qkv_gemm(const float* __restrict__ x, const float* __restrict__ Wc,
              const float* __restrict__ bv,
              float* __restrict__ ko, float* __restrict__ qo, float* __restrict__ vo)
{
    __shared__ float As[16][64];
    __shared__ float Bs[16][64];
    const int tid = threadIdx.x;
    const int tx = tid & 15, ty = tid >> 4;
    const int m0 = blockIdx.y * 64, n0 = blockIdx.x * 64;
    const int lrow = tid >> 2, lk = (tid & 3) * 4;

    float acc[4][4];
#pragma unroll
    for (int i = 0; i < 4; i++)
#pragma unroll
        for (int j = 0; j < 4; j++) acc[i][j] = 0.f;

    for (int k0 = 0; k0 < INn; k0 += 16) {
        float4 av = *(const float4*)(x  + (size_t)(m0 + lrow) * INn + k0 + lk);
        float4 bw = *(const float4*)(Wc + (size_t)(n0 + lrow) * INn + k0 + lk);
        As[lk + 0][lrow] = av.x; As[lk + 1][lrow] = av.y;
        As[lk + 2][lrow] = av.z; As[lk + 3][lrow] = av.w;
        Bs[lk + 0][lrow] = bw.x; Bs[lk + 1][lrow] = bw.y;
        Bs[lk + 2][lrow] = bw.z; Bs[lk + 3][lrow] = bw.w;
        __syncthreads();
#pragma unroll
        for (int kk = 0; kk < 16; kk++) {
            float a[4], b[4];
#pragma unroll
            for (int u = 0; u < 4; u++) { a[u] = As[kk][ty * 4 + u]; b[u] = Bs[kk][tx * 4 + u]; }
#pragma unroll
            for (int i = 0; i < 4; i++)
#pragma unroll
                for (int j = 0; j < 4; j++)
                    acc[i][j] = fmaf(a[i], b[j], acc[i][j]);
        }
        __syncthreads();
    }

#pragma unroll
    for (int i = 0; i < 4; i++) {
        int m = m0 + ty * 4 + i;
#pragma unroll
        for (int j = 0; j < 4; j++) {
            int n = n0 + tx * 4 + j;
            float vv = acc[i][j];
            if (n < 64)       ko[m * 64 + n]       = (vv > 0.f) ? (1.f + vv) : expf(vv);
            else if (n < 128) qo[m * 64 + n - 64]  = (vv > 0.f) ? (1.f + vv) : expf(vv);
            else              vo[m * 64 + n - 128] = vv + bv[n - 128];
        }
    }
}

// ---------------- chunked segmented scan --------------------------------------
__global__ __launch_bounds__(64)
void scan_carry(const float* __restrict__ k, const float* __restrict__ v,
                const int* __restrict__ start,
                float* __restrict__ L, float* __restrict__ Lz, int* __restrict__ keepf)
{
    __shared__ float kbuf[CH];
    __shared__ int   sbuf[CH];
    const int c = blockIdx.x, i = blockIdx.y, j = threadIdx.x;
    const int t0 = c * CH;
    kbuf[j] = k[(size_t)(t0 + j) * Kn + i];
    sbuf[j] = start[t0 + j];
    __syncthreads();

    float run = 0.f, zr = 0.f;
    int anyst = 0;
    for (int tt = 0; tt < CH; tt++) {
        if (sbuf[tt]) { run = 0.f; zr = 0.f; anyst = 1; }
        float kt = kbuf[tt];
        run = fmaf(kt, v[(size_t)(t0 + tt) * Vn + j], run);
        zr += kt;
    }
    L[c * (Kn * Vn) + i * Vn + j] = run;
    if (j == 0) Lz[c * Kn + i] = zr;
    if (i == 0 && j == 0) keepf[c] = !anyst;
}

__global__ __launch_bounds__(1024)
void scan_combine(const float* __restrict__ s0, const float* __restrict__ z0,
                  const float* __restrict__ L, const float* __restrict__ Lz,
                  const int* __restrict__ keepf,
                  float* __restrict__ Sin, float* __restrict__ Zin)
{
    const int tid = threadIdx.x;
    float S[4];
#pragma unroll
    for (int u = 0; u < 4; u++) S[u] = s0[tid * 4 + u];
    float Z = (tid < Kn) ? z0[tid] : 0.f;

    for (int c = 0; c < NCH; c++) {
#pragma unroll
        for (int u = 0; u < 4; u++) Sin[c * (Kn * Vn) + tid * 4 + u] = S[u];
        if (tid < Kn) Zin[c * Kn + tid] = Z;
        int kp = keepf[c];
#pragma unroll
        for (int u = 0; u < 4; u++)
            S[u] = (kp ? S[u] : 0.f) + L[c * (Kn * Vn) + tid * 4 + u];
        if (tid < Kn) Z = (kp ? Z : 0.f) + Lz[c * Kn + tid];
    }
}

__global__ __launch_bounds__(64)
void scan_out(const float* __restrict__ k, const float* __restrict__ v,
              const int* __restrict__ start,
              const float* __restrict__ Sin, const float* __restrict__ Zin,
              float* __restrict__ out_s, float* __restrict__ out_z)
{
    __shared__ float kbuf[CH];
    __shared__ int   sbuf[CH];
    const int c = blockIdx.x, i = blockIdx.y, j = threadIdx.x;
    const int t0 = c * CH;
    kbuf[j] = k[(size_t)(t0 + j) * Kn + i];
    sbuf[j] = start[t0 + j];
    __syncthreads();

    float run = Sin[c * (Kn * Vn) + i * Vn + j];
    float zr  = Zin[c * Kn + i];
    for (int tt = 0; tt < CH; tt++) {
        if (sbuf[tt]) { run = 0.f; zr = 0.f; }
        float kt = kbuf[tt];
        run = fmaf(kt, v[(size_t)(t0 + tt) * Vn + j], run);
        zr += kt;
        out_s[(size_t)(t0 + tt) * (Kn * Vn) + i * Vn + j] = run;
        if (j == 0) out_z[(size_t)(t0 + tt) * Kn + i] = zr;
    }
}

// ---------------- attention output (writes bf16 att) -------------------------
__global__ __launch_bounds__(64)
void attn_kernel(const float* __restrict__ s, const float* __restrict__ z,
                 const float* __restrict__ q, __nv_bfloat16* __restrict__ outp)
{
    __shared__ float qs[64];
    __shared__ float zs[64];
    __shared__ float dsh;

    const int t = blockIdx.x, j = threadIdx.x;
    qs[j] = q[t * 64 + j];
    zs[j] = z[t * 64 + j];
    __syncthreads();
    if (j == 0) {
        float qsum = 0.f, zsum = 0.f;
        for (int i = 0; i < 64; i++) { qsum += qs[i]; zsum += zs[i]; }
        dsh = fmaxf(zsum * qsum, 1e-6f);
    }
    __syncthreads();

    float acc = 0.f;
    const float* sp = s + (size_t)t * 4096;
#pragma unroll 8
    for (int i = 0; i < 64; i++)
        acc = fmaf(sp[i * 64 + j], qs[i], acc);
    outp[t * 64 + j] = __float2bfloat16(acc / dsh);
}

// ---------------- LayerNorm over H ------------------------------------------
__global__ __launch_bounds__(256)
void ln_kernel(const float* __restrict__ h, const float* __restrict__ g,
               const float* __restrict__ b, float* __restrict__ o)
{
    __shared__ float red[256];
    const int t = blockIdx.x, tid = threadIdx.x;
    const float* hp = h + (size_t)t * Hn;

    float loc[16];
    float sum = 0.f;
#pragma unroll
    for (int u = 0; u < 16; u++) { loc[u] = hp[tid + u * 256]; sum += loc[u]; }
    red[tid] = sum; __syncthreads();
    for (int s = 128; s > 0; s >>= 1) { if (tid < s) red[tid] += red[tid + s]; __syncthreads(); }
    float mu = red[0] * (1.f / Hn);
    __syncthreads();

    float sq = 0.f;
#pragma unroll
    for (int u = 0; u < 16; u++) { float d = loc[u] - mu; sq += d * d; }
    red[tid] = sq; __syncthreads();
    for (int s = 128; s > 0; s >>= 1) { if (tid < s) red[tid] += red[tid + s]; __syncthreads(); }
    float inv = rsqrtf(red[0] * (1.f / Hn) + 1e-5f);

#pragma unroll
    for (int u = 0; u < 16; u++) {
        int idx = tid + u * 256;
        o[(size_t)t * Hn + idx] = (loc[u] - mu) * inv * g[idx] + b[idx];
    }
}

// ---------------- launch ----------------------------------------------------
extern "C" void kernel_launch(void* const* d_in, const int* in_sizes, int n_in,
                              void* d_out, int out_size)
{
    const float* x     = (const float*)d_in[0];
    const float* s0    = (const float*)d_in[1];
    const float* z0    = (const float*)d_in[2];
    const int*   start = (const int*)d_in[3];
    const float* Wk    = (const float*)d_in[5];
    const float* Wq    = (const float*)d_in[6];
    const float* Wv    = (const float*)d_in[7];
    const float* bv    = (const float*)d_in[8];
    const float* Wskip = (const float*)d_in[9];
    const float* bskip = (const float*)d_in[10];
    const float* W1    = (const float*)d_in[11];
    const float* b1    = (const float*)d_in[12];
    const float* W2    = (const float*)d_in[13];
    const float* b2    = (const float*)d_in[14];
    const float* W3    = (const float*)d_in[15];
    const float* b3    = (const float*)d_in[16];
    const float* ln_g  = (const float*)d_in[17];
    const float* ln_b  = (const float*)d_in[18];

    float* out    = (float*)d_out;
    float* out_hn = out;
    float* out_s  = out + (size_t)Tn * Hn;
    float* out_z  = out_s + (size_t)Tn * Kn * Vn;

    float *gk, *gq, *gv, *gh3, *gwqkv, *gL, *gSin, *gLz, *gZin;
    int* gkeep;
    __nv_bfloat16 *gattb, *gh1b, *gh2b, *gw1b, *gw2b, *gw3b, *gxcat3, *gwcat3;
    cudaGetSymbolAddress((void**)&gk,     g_k);
    cudaGetSymbolAddress((void**)&gq,     g_q);
    cudaGetSymbolAddress((void**)&gv,     g_v);
    cudaGetSymbolAddress((void**)&gh3,    g_h3);
    cudaGetSymbolAddress((void**)&gwqkv,  g_wqkv);
    cudaGetSymbolAddress((void**)&gattb,  g_attb);
    cudaGetSymbolAddress((void**)&gh1b,   g_h1b);
    cudaGetSymbolAddress((void**)&gh2b,   g_h2b);
    cudaGetSymbolAddress((void**)&gw1b,   g_w1b);
    cudaGetSymbolAddress((void**)&gw2b,   g_w2b);
    cudaGetSymbolAddress((void**)&gw3b,   g_w3b);
    cudaGetSymbolAddress((void**)&gxcat3, g_xcat3);
    cudaGetSymbolAddress((void**)&gwcat3, g_wcat3);
    cudaGetSymbolAddress((void**)&gL,     g_L);
    cudaGetSymbolAddress((void**)&gSin,   g_Sin);
    cudaGetSymbolAddress((void**)&gLz,    g_Lz);
    cudaGetSymbolAddress((void**)&gZin,   g_Zin);
    cudaGetSymbolAddress((void**)&gkeep,  g_keep);

    cudaFuncSetAttribute(gemm_bf16<0>, cudaFuncAttributeMaxDynamicSharedMemorySize, GEMM_SMEM);
    cudaFuncSetAttribute(gemm_bf16<1>, cudaFuncAttributeMaxDynamicSharedMemorySize, GEMM_SMEM);
    cudaFuncSetAttribute(gemm_bf16<2>, cudaFuncAttributeMaxDynamicSharedMemorySize, GEMM_SMEM);

    dim3 blk(256);
    auto grd = [](int M, int N) { return dim3(N / 128, M / 128); };
    auto cgrd = [](int n) { return dim3((n + 255) / 256); };

    cudaMemcpyAsync(gwqkv,             Wk, 64 * INn * 4, cudaMemcpyDeviceToDevice);
    cudaMemcpyAsync(gwqkv +  64 * INn, Wq, 64 * INn * 4, cudaMemcpyDeviceToDevice);
    cudaMemcpyAsync(gwqkv + 128 * INn, Wv, 64 * INn * 4, cudaMemcpyDeviceToDevice);

    f2bf4<<<cgrd(Hn * Vn / 4), blk>>>((const float4*)W1, (uint2*)gw1b, Hn * Vn / 4);
    f2bf4<<<cgrd(Hn * Hn / 4), blk>>>((const float4*)W2, (uint2*)gw2b, Hn * Hn / 4);
    f2bf4<<<cgrd(Hn * Hn / 4), blk>>>((const float4*)W3, (uint2*)gw3b, Hn * Hn / 4);
    split_x3<<<cgrd(Tn * INn), blk>>>(x, gxcat3, Tn * INn);
    split_w3<<<cgrd(Hn * INn), blk>>>(Wskip, gwcat3, Hn * INn);

    qkv_gemm<<<dim3(3, 64), blk>>>(x, gwqkv, bv, gk, gq, gv);

    scan_carry<<<dim3(NCH, Kn), 64>>>(gk, gv, start, gL, gLz, gkeep);
    scan_combine<<<1, 1024>>>(s0, z0, gL, gLz, gkeep, gSin, gZin);
    scan_out<<<dim3(NCH, Kn), 64>>>(gk, gv, start, gSin, gZin, out_s, out_z);

    attn_kernel<<<Tn, 64>>>(out_s, out_z, gq, gattb);

    // MLP on bf16 tensor cores (r14 128x128 tile, 4-stage)
    gemm_bf16<1><<<grd(Tn, Hn), blk, GEMM_SMEM>>>(gattb, gw1b, b1, gh1b, Tn, Hn, Vn);
    gemm_bf16<1><<<grd(Tn, Hn), blk, GEMM_SMEM>>>(gh1b, gw2b, b2, gh2b, Tn, Hn, Hn);
    gemm_bf16<0><<<grd(Tn, Hn), blk, GEMM_SMEM>>>(gh2b, gw3b, b3, gh3, Tn, Hn, Hn);

    // skip: ONE fused split-bf16 GEMM, K=1536 ([xh|xh|xl] . [Wsh|Wsl|Wsh]^T)
    gemm_bf16<2><<<grd(Tn, Hn), blk, GEMM_SMEM>>>(gxcat3, gwcat3, bskip, gh3, Tn, Hn, 3 * INn);

    ln_kernel<<<Tn, 256>>>(gh3, ln_g, ln_b, out_hn);
}